// round 7
// baseline (speedup 1.0000x reference)
#include <cuda_runtime.h>
#include <cuda_fp16.h>
#include <cstdint>

#define TOKENS 4096
#define DM 1024
#define DF 4096
#define NE 8

// ---------------- device scratch (static, no runtime alloc) ----------------
__device__ int g_cnt[NE];
__device__ int g_tok[NE][TOKENS];
__device__ int g_slot[NE][TOKENS];
__device__ __align__(16) __half g_xh[(size_t)TOKENS * DM];
__device__ __align__(16) __half g_w1h[(size_t)NE * DF * DM];   // [E][N=DF][K=DM]
__device__ __align__(16) __half g_w1l[(size_t)NE * DF * DM];
__device__ __align__(16) __half g_w2h[(size_t)NE * DM * DF];   // [E][N=DM][K=DF]
__device__ __align__(16) __half g_w2l[(size_t)NE * DM * DF];
__device__ __align__(16) __half g_hh[(size_t)NE * TOKENS * DF];
__device__ __align__(16) float  g_buf[(size_t)2 * TOKENS * DM];

// ---------------- helpers ----------------
__device__ __forceinline__ uint32_t smem_u32(const void* p) {
    uint32_t a;
    asm("{ .reg .u64 t; cvta.to.shared.u64 t, %1; cvt.u32.u64 %0, t; }" : "=r"(a) : "l"(p));
    return a;
}
__device__ __forceinline__ void cp16(uint32_t s, const void* g) {
    asm volatile("cp.async.cg.shared.global [%0], [%1], 16;" :: "r"(s), "l"(g) : "memory");
}
__device__ __forceinline__ void cp_commit() {
    asm volatile("cp.async.commit_group;" ::: "memory");
}
__device__ __forceinline__ void cp_wait0() {
    asm volatile("cp.async.wait_group 0;" ::: "memory");
}
#define MMA_F16(acc, a, b)                                                       \
    asm volatile(                                                                \
        "mma.sync.aligned.m16n8k16.row.col.f32.f16.f16.f32 "                     \
        "{%0,%1,%2,%3},{%4,%5,%6,%7},{%8,%9},{%0,%1,%2,%3};"                     \
        : "+f"((acc)[0]), "+f"((acc)[1]), "+f"((acc)[2]), "+f"((acc)[3])         \
        : "r"((a)[0]), "r"((a)[1]), "r"((a)[2]), "r"((a)[3]),                    \
          "r"((b)[0]), "r"((b)[1]))
#define LDSM4(r0, r1, r2, r3, addr)                                              \
    asm volatile("ldmatrix.sync.aligned.m8n8.x4.shared.b16 {%0,%1,%2,%3}, [%4];" \
                 : "=r"(r0), "=r"(r1), "=r"(r2), "=r"(r3) : "r"(addr))

// fp32 -> fp16 hi + lo residual
__device__ __forceinline__ void splitf16(float a, __half& h, __half& l) {
    h = __float2half_rn(a);
    l = __float2half_rn(a - __half2float(h));
}

// ---------------- 0) zero counters ----------------
__global__ void zero_cnt_kernel() {
    if (threadIdx.x < NE) g_cnt[threadIdx.x] = 0;
}

// ---------------- 1) routing ----------------
__global__ void route_kernel(const float* __restrict__ x,
                             const float* __restrict__ Wg,
                             const float* __restrict__ bg) {
    int warp = threadIdx.x >> 5;
    int lane = threadIdx.x & 31;
    int token = blockIdx.x * 8 + warp;
    if (token >= TOKENS) return;

    float acc[NE];
#pragma unroll
    for (int e = 0; e < NE; e++) acc[e] = 0.f;
    const float* xrow = x + (size_t)token * DM;
    for (int k = lane; k < DM; k += 32) {
        float xv = xrow[k];
        const float* wr = Wg + (size_t)k * NE;
#pragma unroll
        for (int e = 0; e < NE; e++) acc[e] += xv * wr[e];
    }
#pragma unroll
    for (int e = 0; e < NE; e++)
#pragma unroll
        for (int o = 16; o > 0; o >>= 1)
            acc[e] += __shfl_xor_sync(0xffffffffu, acc[e], o);
    if (lane == 0) {
        float lg[NE];
#pragma unroll
        for (int e = 0; e < NE; e++) lg[e] = acc[e] + bg[e];
        int e0 = 0;
#pragma unroll
        for (int e = 1; e < NE; e++) if (lg[e] > lg[e0]) e0 = e;
        int e1 = (e0 == 0) ? 1 : 0;
#pragma unroll
        for (int e = 0; e < NE; e++) if (e != e0 && lg[e] > lg[e1]) e1 = e;
        int p0 = atomicAdd(&g_cnt[e0], 1);
        g_tok[e0][p0] = token; g_slot[e0][p0] = 0;
        int p1 = atomicAdd(&g_cnt[e1], 1);
        g_tok[e1][p1] = token; g_slot[e1][p1] = 1;
    }
}

// ---------------- 2) converts ----------------
// x: fp32 -> fp16 hi only (A-side; residual term is dropped by design)
__global__ void convert_x_kernel(const float* __restrict__ x) {
    int i = blockIdx.x * blockDim.x + threadIdx.x;   // float4 index
    float4 v = ((const float4*)x)[i];
    __half2 h0, h1;
    h0.x = __float2half_rn(v.x); h0.y = __float2half_rn(v.y);
    h1.x = __float2half_rn(v.z); h1.y = __float2half_rn(v.w);
    ((__half2*)g_xh)[2 * i]     = h0;
    ((__half2*)g_xh)[2 * i + 1] = h1;
}

// transpose + split: W [E][K][N] fp32 -> [E][N][K] fp16 hi/lo
template <int K, int N, bool W1SEL>
__global__ void convert_w_kernel(const float* __restrict__ W) {
    __shared__ float t[32][33];
    __half* Oh = W1SEL ? g_w1h : g_w2h;
    __half* Ol = W1SEL ? g_w1l : g_w2l;
    int e = blockIdx.z;
    int n0 = blockIdx.x * 32, k0 = blockIdx.y * 32;
    int tx = threadIdx.x, ty = threadIdx.y;  // 32 x 8
    const float* Wp = W + (size_t)e * K * N;
#pragma unroll
    for (int i = 0; i < 4; i++)
        t[ty + 8 * i][tx] = Wp[(size_t)(k0 + ty + 8 * i) * N + n0 + tx];
    __syncthreads();
    __half* oh = Oh + (size_t)e * N * K;
    __half* ol = Ol + (size_t)e * N * K;
    int n_l = (threadIdx.y * 4) + (tx >> 3);        // 0..31
    int k_l = (tx & 7) * 2;                          // even k, pairs
#pragma unroll
    for (int rep = 0; rep < 2; rep++) {
        int kk = k_l + rep * 16;
        float v0 = t[kk][n_l];
        float v1 = t[kk + 1][n_l];
        __half2 h, l;
        splitf16(v0, h.x, l.x);
        splitf16(v1, h.y, l.y);
        size_t o = (size_t)(n0 + n_l) * K + k0 + kk;
        *(__half2*)(oh + o) = h;
        *(__half2*)(ol + o) = l;
    }
}

// ---------------- 3) fp16 2-MMA split grouped GEMM (ldmatrix frag loads) ----
// BM=128, BN=128, BK=32. 256 threads = 8 warps (2 M x 4 N), warp tile 64x32.
// SMEM stage: A | Bh | Bl, each 128 rows x 40 fp16 (80B padded rows).
// 2-stage cp.async, occupancy 2, low-liveness fragment loop.
#define ROWB   80
#define TILEB  (128 * ROWB)          // 10240 B
#define STAGEB (3 * TILEB)           // 30720 B
#define SMEMB  (2 * STAGEB + 512)    // 61952 B; 2 CTAs = 124KB < 228KB

template <int KDIM>
__device__ __forceinline__ void stage_load(uint32_t sb, int k0,
                                           const __half* __restrict__ A,
                                           const __half* __restrict__ Bh,
                                           const __half* __restrict__ Bl,
                                           const int* __restrict__ srow, int n0, int tid) {
#pragma unroll
    for (int half_ = 0; half_ < 2; half_++) {
        int c = tid + half_ * 256;       // 0..511
        int r = c >> 2, j = c & 3;
        uint32_t so = (uint32_t)(r * ROWB + j * 16);
        size_t ga = (size_t)srow[r] * KDIM + k0 + j * 8;
        size_t gb = (size_t)(n0 + r) * KDIM + k0 + j * 8;
        cp16(sb + so,             A + ga);
        cp16(sb + TILEB + so,     Bh + gb);
        cp16(sb + 2 * TILEB + so, Bl + gb);
    }
}

template <int KDIM, int NDIM, bool G1>
__global__ void __launch_bounds__(256, 2)
moe_gemm(const float* __restrict__ bias) {
    const int e = blockIdx.z;
    const int cnt = g_cnt[e];
    const int m0 = blockIdx.y * 128;
    if (m0 >= cnt) return;
    const int n0 = blockIdx.x * 128;
    constexpr int NT = KDIM / 32;

    extern __shared__ char smem[];
    const uint32_t sb = smem_u32(smem);
    const int tid = threadIdx.x, wid = tid >> 5, lane = tid & 31;
    const int warp_m = wid >> 2, warp_n = wid & 3;
    const int g = lane >> 2, tg = lane & 3;
    int* srow = (int*)(smem + 2 * STAGEB);

    if (tid < 128) {
        int rr = min(m0 + tid, cnt - 1);
        srow[tid] = G1 ? g_tok[e][rr] : (e * TOKENS + rr);
    }
    __syncthreads();

    const __half* A  = G1 ? g_xh : g_hh;
    const __half* Bh = (G1 ? g_w1h : g_w2h) + (size_t)e * NDIM * KDIM;
    const __half* Bl = (G1 ? g_w1l : g_w2l) + (size_t)e * NDIM * KDIM;

    float acc[4][4][4];
#pragma unroll
    for (int i = 0; i < 4; i++)
#pragma unroll
        for (int j = 0; j < 4; j++)
#pragma unroll
            for (int k = 0; k < 4; k++) acc[i][j][k] = 0.f;

    stage_load<KDIM>(sb, 0, A, Bh, Bl, srow, n0, tid);
    cp_commit();

    // ldmatrix per-lane addressing (verified in R4):
    // lanes 0-15 -> rows (m or n) 0-15 at k-lo; lanes 16-31 -> same rows, +16B (k-hi)
    const int lrow = lane & 15;
    const uint32_t khoff = (uint32_t)(lane >> 4) * 16;
    const uint32_t aOffBase = (uint32_t)((warp_m * 64 + lrow) * ROWB) + khoff;
    const uint32_t bOffBase = (uint32_t)((warp_n * 32 + lrow) * ROWB) + khoff;

    for (int it = 0; it < NT; it++) {
        cp_wait0();
        __syncthreads();
        if (it + 1 < NT) {
            stage_load<KDIM>(sb + ((it + 1) & 1) * STAGEB, (it + 1) * 32,
                             A, Bh, Bl, srow, n0, tid);
            cp_commit();
        }
        const uint32_t st = sb + (it & 1) * STAGEB;
#pragma unroll
        for (int ks = 0; ks < 2; ks++) {
            const uint32_t kb = (uint32_t)ks * 32;
            uint32_t bh[4][2], bl[4][2];
#pragma unroll
            for (int p = 0; p < 2; p++) {
                uint32_t bd = st + TILEB + bOffBase + p * (16 * ROWB) + kb;
                LDSM4(bh[2 * p][0], bh[2 * p + 1][0], bh[2 * p][1], bh[2 * p + 1][1], bd);
                LDSM4(bl[2 * p][0], bl[2 * p + 1][0], bl[2 * p][1], bl[2 * p + 1][1], bd + TILEB);
            }
#pragma unroll
            for (int mf = 0; mf < 4; mf++) {
                uint32_t ad = st + aOffBase + mf * (16 * ROWB) + kb;
                uint32_t a[4];
                LDSM4(a[0], a[1], a[2], a[3], ad);
#pragma unroll
                for (int nf = 0; nf < 4; nf++) {
                    MMA_F16(acc[mf][nf], a, bh[nf]);
                    MMA_F16(acc[mf][nf], a, bl[nf]);
                }
            }
        }
        __syncthreads();
    }

    // ---------------- epilogue ----------------
#pragma unroll
    for (int mf = 0; mf < 4; mf++) {
        int r0 = m0 + warp_m * 64 + mf * 16 + g;
        int r1 = r0 + 8;
#pragma unroll
        for (int nf = 0; nf < 4; nf++) {
            int col = n0 + warp_n * 32 + nf * 8 + tg * 2;
            float bv0 = bias[e * NDIM + col];
            float bv1 = bias[e * NDIM + col + 1];
#pragma unroll
            for (int h = 0; h < 2; h++) {
                int r = h ? r1 : r0;
                if (r >= cnt) continue;
                float v0 = acc[mf][nf][2 * h]     + bv0;
                float v1 = acc[mf][nf][2 * h + 1] + bv1;
                if (G1) {
                    v0 = fmaxf(v0, 0.f);
                    v1 = fmaxf(v1, 0.f);
                    __half2 hh;
                    hh.x = __float2half_rn(v0);
                    hh.y = __float2half_rn(v1);
                    size_t o = ((size_t)(e * TOKENS + r)) * DF + col;
                    *(__half2*)(g_hh + o) = hh;
                } else {
                    int token = g_tok[e][r];
                    int slot  = g_slot[e][r];
                    float* dst = g_buf + ((size_t)slot * TOKENS + token) * DM + col;
                    *(float2*)dst = make_float2(v0, v1);
                }
            }
        }
    }
}

// ---------------- 4) combine ----------------
__global__ void combine_kernel(float* __restrict__ out) {
    int i = blockIdx.x * blockDim.x + threadIdx.x;
    const float4* b0 = (const float4*)g_buf;
    const float4* b1 = (const float4*)(g_buf + (size_t)TOKENS * DM);
    float4 u = b0[i], v = b1[i];
    ((float4*)out)[i] = make_float4(u.x + v.x, u.y + v.y, u.z + v.z, u.w + v.w);
}

// ---------------- host ----------------
extern "C" void kernel_launch(void* const* d_in, const int* in_sizes, int n_in,
                              void* d_out, int out_size) {
    const float* x  = (const float*)d_in[0];
    const float* Wg = (const float*)d_in[1];
    const float* bg = (const float*)d_in[2];
    const float* W1 = (const float*)d_in[3];
    const float* b1 = (const float*)d_in[4];
    const float* W2 = (const float*)d_in[5];
    const float* b2 = (const float*)d_in[6];
    float* out = (float*)d_out;

    cudaFuncSetAttribute(moe_gemm<DM, DF, true>,
                         cudaFuncAttributeMaxDynamicSharedMemorySize, SMEMB);
    cudaFuncSetAttribute(moe_gemm<DF, DM, false>,
                         cudaFuncAttributeMaxDynamicSharedMemorySize, SMEMB);

    zero_cnt_kernel<<<1, 32>>>();
    route_kernel<<<TOKENS / 8, 256>>>(x, Wg, bg);

    convert_x_kernel<<<TOKENS * DM / 4 / 256, 256>>>(x);
    convert_w_kernel<DM, DF, true><<<dim3(DF / 32, DM / 32, NE), dim3(32, 8)>>>(W1);
    convert_w_kernel<DF, DM, false><<<dim3(DM / 32, DF / 32, NE), dim3(32, 8)>>>(W2);

    // GEMM1: h = relu(gather(x) @ W1[e] + b1[e]) -> g_hh (fp16)
    moe_gemm<DM, DF, true><<<dim3(DF / 128, TOKENS / 128, NE), 256, SMEMB>>>(b1);
    // GEMM2: y = h @ W2[e] + b2[e] -> scatter into g_buf
    moe_gemm<DF, DM, false><<<dim3(DM / 128, TOKENS / 128, NE), 256, SMEMB>>>(b2);

    combine_kernel<<<(TOKENS * DM / 4) / 256, 256>>>(out);
}

// round 8
// speedup vs baseline: 1.2443x; 1.2443x over previous
#include <cuda_runtime.h>
#include <cuda_fp16.h>
#include <cstdint>

#define TOKENS 4096
#define DM 1024
#define DF 4096
#define NE 8

// ---------------- device scratch (static, no runtime alloc) ----------------
__device__ int g_cnt[NE];
__device__ int g_tok[NE][TOKENS];
__device__ int g_slot[NE][TOKENS];
__device__ __align__(16) __half g_xh[(size_t)TOKENS * DM];
__device__ __align__(16) __half g_w1h[(size_t)NE * DF * DM];   // [E][N=DF][K=DM]
__device__ __align__(16) __half g_w1l[(size_t)NE * DF * DM];
__device__ __align__(16) __half g_w2h[(size_t)NE * DM * DF];   // [E][N=DM][K=DF]
__device__ __align__(16) __half g_hh[(size_t)NE * TOKENS * DF];
__device__ __align__(16) float  g_buf[(size_t)2 * TOKENS * DM];

// ---------------- helpers ----------------
__device__ __forceinline__ uint32_t smem_u32(const void* p) {
    uint32_t a;
    asm("{ .reg .u64 t; cvta.to.shared.u64 t, %1; cvt.u32.u64 %0, t; }" : "=r"(a) : "l"(p));
    return a;
}
__device__ __forceinline__ void cp16(uint32_t s, const void* g) {
    asm volatile("cp.async.cg.shared.global [%0], [%1], 16;" :: "r"(s), "l"(g) : "memory");
}
__device__ __forceinline__ void cp_commit() {
    asm volatile("cp.async.commit_group;" ::: "memory");
}
__device__ __forceinline__ void cp_wait0() {
    asm volatile("cp.async.wait_group 0;" ::: "memory");
}
#define MMA_F16(acc, a, b)                                                       \
    asm volatile(                                                                \
        "mma.sync.aligned.m16n8k16.row.col.f32.f16.f16.f32 "                     \
        "{%0,%1,%2,%3},{%4,%5,%6,%7},{%8,%9},{%0,%1,%2,%3};"                     \
        : "+f"((acc)[0]), "+f"((acc)[1]), "+f"((acc)[2]), "+f"((acc)[3])         \
        : "r"((a)[0]), "r"((a)[1]), "r"((a)[2]), "r"((a)[3]),                    \
          "r"((b)[0]), "r"((b)[1]))

// fp32 -> fp16 hi + lo residual
__device__ __forceinline__ void splitf16(float a, __half& h, __half& l) {
    h = __float2half_rn(a);
    l = __float2half_rn(a - __half2float(h));
}

// ---------------- 0) zero counters ----------------
__global__ void zero_cnt_kernel() {
    if (threadIdx.x < NE) g_cnt[threadIdx.x] = 0;
}

// ---------------- 1) routing ----------------
__global__ void route_kernel(const float* __restrict__ x,
                             const float* __restrict__ Wg,
                             const float* __restrict__ bg) {
    int warp = threadIdx.x >> 5;
    int lane = threadIdx.x & 31;
    int token = blockIdx.x * 8 + warp;
    if (token >= TOKENS) return;

    float acc[NE];
#pragma unroll
    for (int e = 0; e < NE; e++) acc[e] = 0.f;
    const float* xrow = x + (size_t)token * DM;
    for (int k = lane; k < DM; k += 32) {
        float xv = xrow[k];
        const float* wr = Wg + (size_t)k * NE;
#pragma unroll
        for (int e = 0; e < NE; e++) acc[e] += xv * wr[e];
    }
#pragma unroll
    for (int e = 0; e < NE; e++)
#pragma unroll
        for (int o = 16; o > 0; o >>= 1)
            acc[e] += __shfl_xor_sync(0xffffffffu, acc[e], o);
    if (lane == 0) {
        float lg[NE];
#pragma unroll
        for (int e = 0; e < NE; e++) lg[e] = acc[e] + bg[e];
        int e0 = 0;
#pragma unroll
        for (int e = 1; e < NE; e++) if (lg[e] > lg[e0]) e0 = e;
        int e1 = (e0 == 0) ? 1 : 0;
#pragma unroll
        for (int e = 0; e < NE; e++) if (e != e0 && lg[e] > lg[e1]) e1 = e;
        int p0 = atomicAdd(&g_cnt[e0], 1);
        g_tok[e0][p0] = token; g_slot[e0][p0] = 0;
        int p1 = atomicAdd(&g_cnt[e1], 1);
        g_tok[e1][p1] = token; g_slot[e1][p1] = 1;
    }
}

// ---------------- 2) converts ----------------
// x: fp32 -> fp16 hi only (A-side; residual term is dropped by design)
__global__ void convert_x_kernel(const float* __restrict__ x) {
    int i = blockIdx.x * blockDim.x + threadIdx.x;   // float4 index
    float4 v = ((const float4*)x)[i];
    __half2 h0, h1;
    h0.x = __float2half_rn(v.x); h0.y = __float2half_rn(v.y);
    h1.x = __float2half_rn(v.z); h1.y = __float2half_rn(v.w);
    ((__half2*)g_xh)[2 * i]     = h0;
    ((__half2*)g_xh)[2 * i + 1] = h1;
}

// transpose + split: W1 [E][K][N] fp32 -> [E][N][K] fp16 hi/lo (both terms kept)
template <int K, int N>
__global__ void convert_w1_kernel(const float* __restrict__ W) {
    __shared__ float t[32][33];
    int e = blockIdx.z;
    int n0 = blockIdx.x * 32, k0 = blockIdx.y * 32;
    int tx = threadIdx.x, ty = threadIdx.y;  // 32 x 8
    const float* Wp = W + (size_t)e * K * N;
#pragma unroll
    for (int i = 0; i < 4; i++)
        t[ty + 8 * i][tx] = Wp[(size_t)(k0 + ty + 8 * i) * N + n0 + tx];
    __syncthreads();
    __half* oh = g_w1h + (size_t)e * N * K;
    __half* ol = g_w1l + (size_t)e * N * K;
    int n_l = (threadIdx.y * 4) + (tx >> 3);        // 0..31
    int k_l = (tx & 7) * 2;                          // even k, pairs
#pragma unroll
    for (int rep = 0; rep < 2; rep++) {
        int kk = k_l + rep * 16;
        float v0 = t[kk][n_l];
        float v1 = t[kk + 1][n_l];
        __half2 h, l;
        splitf16(v0, h.x, l.x);
        splitf16(v1, h.y, l.y);
        size_t o = (size_t)(n0 + n_l) * K + k0 + kk;
        *(__half2*)(oh + o) = h;
        *(__half2*)(ol + o) = l;
    }
}

// transpose: W2 [E][K][N] fp32 -> [E][N][K] fp16 hi only (residual dropped)
template <int K, int N>
__global__ void convert_w2_kernel(const float* __restrict__ W) {
    __shared__ float t[32][33];
    int e = blockIdx.z;
    int n0 = blockIdx.x * 32, k0 = blockIdx.y * 32;
    int tx = threadIdx.x, ty = threadIdx.y;  // 32 x 8
    const float* Wp = W + (size_t)e * K * N;
#pragma unroll
    for (int i = 0; i < 4; i++)
        t[ty + 8 * i][tx] = Wp[(size_t)(k0 + ty + 8 * i) * N + n0 + tx];
    __syncthreads();
    __half* oh = g_w2h + (size_t)e * N * K;
    int n_l = (threadIdx.y * 4) + (tx >> 3);
    int k_l = (tx & 7) * 2;
#pragma unroll
    for (int rep = 0; rep < 2; rep++) {
        int kk = k_l + rep * 16;
        __half2 h;
        h.x = __float2half_rn(t[kk][n_l]);
        h.y = __float2half_rn(t[kk + 1][n_l]);
        size_t o = (size_t)(n0 + n_l) * K + k0 + kk;
        *(__half2*)(oh + o) = h;
    }
}

// ---------------- 3) fp16 split grouped GEMM (R6-proven scalar-LDS mainloop) -
// BM=128, BN=128, BK=32. 256 threads = 8 warps (2 M x 4 N), warp tile 64x32.
// GEMM1 (BLO=1): stage = A | Bh | Bl (3 tiles), 2 MMA per frag pair.
// GEMM2 (BLO=0): stage = A | Bh      (2 tiles), 1 MMA per frag pair.
// 2-stage cp.async, occupancy 2, low-liveness fragment loop.
#define ROWB   80
#define TILEB  (128 * ROWB)          // 10240 B

template <int KDIM, bool BLO>
__device__ __forceinline__ void stage_load(uint32_t sb, int k0,
                                           const __half* __restrict__ A,
                                           const __half* __restrict__ Bh,
                                           const __half* __restrict__ Bl,
                                           const int* __restrict__ srow, int n0, int tid) {
#pragma unroll
    for (int half_ = 0; half_ < 2; half_++) {
        int c = tid + half_ * 256;       // 0..511
        int r = c >> 2, j = c & 3;
        uint32_t so = (uint32_t)(r * ROWB + j * 16);
        size_t ga = (size_t)srow[r] * KDIM + k0 + j * 8;
        size_t gb = (size_t)(n0 + r) * KDIM + k0 + j * 8;
        cp16(sb + so,         A + ga);
        cp16(sb + TILEB + so, Bh + gb);
        if (BLO) cp16(sb + 2 * TILEB + so, Bl + gb);
    }
}

template <int KDIM, int NDIM, bool G1>
__global__ void __launch_bounds__(256, 2)
moe_gemm(const float* __restrict__ bias) {
    constexpr bool BLO = G1;                         // GEMM1 keeps Bl; GEMM2 drops it
    constexpr int STAGEB = (BLO ? 3 : 2) * TILEB;
    const int e = blockIdx.z;
    const int cnt = g_cnt[e];
    const int m0 = blockIdx.y * 128;
    if (m0 >= cnt) return;
    const int n0 = blockIdx.x * 128;
    constexpr int NT = KDIM / 32;

    extern __shared__ char smem[];
    const uint32_t sb = smem_u32(smem);
    const int tid = threadIdx.x, wid = tid >> 5, lane = tid & 31;
    const int warp_m = wid >> 2, warp_n = wid & 3;
    const int g = lane >> 2, tg = lane & 3;
    int* srow = (int*)(smem + 2 * STAGEB);

    if (tid < 128) {
        int rr = min(m0 + tid, cnt - 1);
        srow[tid] = G1 ? g_tok[e][rr] : (e * TOKENS + rr);
    }
    __syncthreads();

    const __half* A  = G1 ? g_xh : g_hh;
    const __half* Bh = (G1 ? g_w1h : g_w2h) + (size_t)e * NDIM * KDIM;
    const __half* Bl = G1 ? (g_w1l + (size_t)e * NDIM * KDIM) : nullptr;

    float acc[4][4][4];
#pragma unroll
    for (int i = 0; i < 4; i++)
#pragma unroll
        for (int j = 0; j < 4; j++)
#pragma unroll
            for (int k = 0; k < 4; k++) acc[i][j][k] = 0.f;

    stage_load<KDIM, BLO>(sb, 0, A, Bh, Bl, srow, n0, tid);
    cp_commit();

    const int aRowBase = warp_m * 64 + g;
    const int bRowBase = warp_n * 32 + g;

    for (int it = 0; it < NT; it++) {
        cp_wait0();
        __syncthreads();
        if (it + 1 < NT) {
            stage_load<KDIM, BLO>(sb + ((it + 1) & 1) * STAGEB, (it + 1) * 32,
                                  A, Bh, Bl, srow, n0, tid);
            cp_commit();
        }
        const char* st = smem + (it & 1) * STAGEB;
#pragma unroll
        for (int ks = 0; ks < 2; ks++) {
            const int colb = (ks * 16 + tg * 2) * 2;   // byte offset within row
            uint32_t bh[4][2], bl[4][2];
#pragma unroll
            for (int nf = 0; nf < 4; nf++) {
                int ro = (bRowBase + nf * 8) * ROWB + colb;
                bh[nf][0] = *(const uint32_t*)(st + TILEB + ro);
                bh[nf][1] = *(const uint32_t*)(st + TILEB + ro + 16);
                if (BLO) {
                    bl[nf][0] = *(const uint32_t*)(st + 2 * TILEB + ro);
                    bl[nf][1] = *(const uint32_t*)(st + 2 * TILEB + ro + 16);
                }
            }
#pragma unroll
            for (int mf = 0; mf < 4; mf++) {
                int ro = (aRowBase + mf * 16) * ROWB + colb;
                uint32_t a[4];
                a[0] = *(const uint32_t*)(st + ro);
                a[1] = *(const uint32_t*)(st + ro + 8 * ROWB);
                a[2] = *(const uint32_t*)(st + ro + 16);
                a[3] = *(const uint32_t*)(st + ro + 8 * ROWB + 16);
#pragma unroll
                for (int nf = 0; nf < 4; nf++) {
                    MMA_F16(acc[mf][nf], a, bh[nf]);
                    if (BLO) MMA_F16(acc[mf][nf], a, bl[nf]);
                }
            }
        }
        __syncthreads();
    }

    // ---------------- epilogue ----------------
#pragma unroll
    for (int mf = 0; mf < 4; mf++) {
        int r0 = m0 + warp_m * 64 + mf * 16 + g;
        int r1 = r0 + 8;
#pragma unroll
        for (int nf = 0; nf < 4; nf++) {
            int col = n0 + warp_n * 32 + nf * 8 + tg * 2;
            float bv0 = bias[e * NDIM + col];
            float bv1 = bias[e * NDIM + col + 1];
#pragma unroll
            for (int h = 0; h < 2; h++) {
                int r = h ? r1 : r0;
                if (r >= cnt) continue;
                float v0 = acc[mf][nf][2 * h]     + bv0;
                float v1 = acc[mf][nf][2 * h + 1] + bv1;
                if (G1) {
                    v0 = fmaxf(v0, 0.f);
                    v1 = fmaxf(v1, 0.f);
                    __half2 hh;
                    hh.x = __float2half_rn(v0);
                    hh.y = __float2half_rn(v1);
                    size_t o = ((size_t)(e * TOKENS + r)) * DF + col;
                    *(__half2*)(g_hh + o) = hh;
                } else {
                    int token = g_tok[e][r];
                    int slot  = g_slot[e][r];
                    float* dst = g_buf + ((size_t)slot * TOKENS + token) * DM + col;
                    *(float2*)dst = make_float2(v0, v1);
                }
            }
        }
    }
}

#define SMEMB1 (2 * (3 * TILEB) + 512)   // 61952 B
#define SMEMB2 (2 * (2 * TILEB) + 512)   // 41472 B

// ---------------- 4) combine ----------------
__global__ void combine_kernel(float* __restrict__ out) {
    int i = blockIdx.x * blockDim.x + threadIdx.x;
    const float4* b0 = (const float4*)g_buf;
    const float4* b1 = (const float4*)(g_buf + (size_t)TOKENS * DM);
    float4 u = b0[i], v = b1[i];
    ((float4*)out)[i] = make_float4(u.x + v.x, u.y + v.y, u.z + v.z, u.w + v.w);
}

// ---------------- host ----------------
extern "C" void kernel_launch(void* const* d_in, const int* in_sizes, int n_in,
                              void* d_out, int out_size) {
    const float* x  = (const float*)d_in[0];
    const float* Wg = (const float*)d_in[1];
    const float* bg = (const float*)d_in[2];
    const float* W1 = (const float*)d_in[3];
    const float* b1 = (const float*)d_in[4];
    const float* W2 = (const float*)d_in[5];
    const float* b2 = (const float*)d_in[6];
    float* out = (float*)d_out;

    cudaFuncSetAttribute(moe_gemm<DM, DF, true>,
                         cudaFuncAttributeMaxDynamicSharedMemorySize, SMEMB1);
    cudaFuncSetAttribute(moe_gemm<DF, DM, false>,
                         cudaFuncAttributeMaxDynamicSharedMemorySize, SMEMB2);

    zero_cnt_kernel<<<1, 32>>>();
    route_kernel<<<TOKENS / 8, 256>>>(x, Wg, bg);

    convert_x_kernel<<<TOKENS * DM / 4 / 256, 256>>>(x);
    convert_w1_kernel<DM, DF><<<dim3(DF / 32, DM / 32, NE), dim3(32, 8)>>>(W1);
    convert_w2_kernel<DF, DM><<<dim3(DM / 32, DF / 32, NE), dim3(32, 8)>>>(W2);

    // GEMM1: h = relu(gather(x) @ (W1h+W1l) + b1) -> g_hh (fp16)
    moe_gemm<DM, DF, true><<<dim3(DF / 128, TOKENS / 128, NE), 256, SMEMB1>>>(b1);
    // GEMM2: y = h @ W2h + b2 -> scatter into g_buf (single-MMA path)
    moe_gemm<DF, DM, false><<<dim3(DM / 128, TOKENS / 128, NE), 256, SMEMB2>>>(b2);

    combine_kernel<<<(TOKENS * DM / 4) / 256, 256>>>(out);
}

// round 9
// speedup vs baseline: 1.4563x; 1.1704x over previous
#include <cuda_runtime.h>
#include <cuda_fp16.h>
#include <cstdint>

#define TOKENS 4096
#define DM 1024
#define DF 4096
#define NE 8

// ---------------- device scratch (static, no runtime alloc) ----------------
__device__ int g_cnt[NE];
__device__ int g_tok[NE][TOKENS];
__device__ int g_slot[NE][TOKENS];
__device__ __align__(16) __half g_xh[(size_t)TOKENS * DM];
__device__ __align__(16) __half g_w1h[(size_t)NE * DF * DM];   // [E][N=DF][K=DM]
__device__ __align__(16) __half g_w2h[(size_t)NE * DM * DF];   // [E][N=DM][K=DF]
__device__ __align__(16) __half g_hh[(size_t)NE * TOKENS * DF];
__device__ __align__(16) float  g_buf[(size_t)2 * TOKENS * DM];

// ---------------- helpers ----------------
__device__ __forceinline__ uint32_t smem_u32(const void* p) {
    uint32_t a;
    asm("{ .reg .u64 t; cvta.to.shared.u64 t, %1; cvt.u32.u64 %0, t; }" : "=r"(a) : "l"(p));
    return a;
}
__device__ __forceinline__ void cp16(uint32_t s, const void* g) {
    asm volatile("cp.async.cg.shared.global [%0], [%1], 16;" :: "r"(s), "l"(g) : "memory");
}
__device__ __forceinline__ void cp_commit() {
    asm volatile("cp.async.commit_group;" ::: "memory");
}
__device__ __forceinline__ void cp_wait0() {
    asm volatile("cp.async.wait_group 0;" ::: "memory");
}
#define MMA_F16(acc, a, b)                                                       \
    asm volatile(                                                                \
        "mma.sync.aligned.m16n8k16.row.col.f32.f16.f16.f32 "                     \
        "{%0,%1,%2,%3},{%4,%5,%6,%7},{%8,%9},{%0,%1,%2,%3};"                     \
        : "+f"((acc)[0]), "+f"((acc)[1]), "+f"((acc)[2]), "+f"((acc)[3])         \
        : "r"((a)[0]), "r"((a)[1]), "r"((a)[2]), "r"((a)[3]),                    \
          "r"((b)[0]), "r"((b)[1]))

// ---------------- 0) zero counters ----------------
__global__ void zero_cnt_kernel() {
    if (threadIdx.x < NE) g_cnt[threadIdx.x] = 0;
}

// ---------------- 1) routing ----------------
__global__ void route_kernel(const float* __restrict__ x,
                             const float* __restrict__ Wg,
                             const float* __restrict__ bg) {
    int warp = threadIdx.x >> 5;
    int lane = threadIdx.x & 31;
    int token = blockIdx.x * 8 + warp;
    if (token >= TOKENS) return;

    float acc[NE];
#pragma unroll
    for (int e = 0; e < NE; e++) acc[e] = 0.f;
    const float* xrow = x + (size_t)token * DM;
    for (int k = lane; k < DM; k += 32) {
        float xv = xrow[k];
        const float* wr = Wg + (size_t)k * NE;
#pragma unroll
        for (int e = 0; e < NE; e++) acc[e] += xv * wr[e];
    }
#pragma unroll
    for (int e = 0; e < NE; e++)
#pragma unroll
        for (int o = 16; o > 0; o >>= 1)
            acc[e] += __shfl_xor_sync(0xffffffffu, acc[e], o);
    if (lane == 0) {
        float lg[NE];
#pragma unroll
        for (int e = 0; e < NE; e++) lg[e] = acc[e] + bg[e];
        int e0 = 0;
#pragma unroll
        for (int e = 1; e < NE; e++) if (lg[e] > lg[e0]) e0 = e;
        int e1 = (e0 == 0) ? 1 : 0;
#pragma unroll
        for (int e = 0; e < NE; e++) if (e != e0 && lg[e] > lg[e1]) e1 = e;
        int p0 = atomicAdd(&g_cnt[e0], 1);
        g_tok[e0][p0] = token; g_slot[e0][p0] = 0;
        int p1 = atomicAdd(&g_cnt[e1], 1);
        g_tok[e1][p1] = token; g_slot[e1][p1] = 1;
    }
}

// ---------------- 2) converts ----------------
// x: fp32 -> fp16 (residual dropped by design)
__global__ void convert_x_kernel(const float* __restrict__ x) {
    int i = blockIdx.x * blockDim.x + threadIdx.x;   // float4 index
    float4 v = ((const float4*)x)[i];
    __half2 h0, h1;
    h0.x = __float2half_rn(v.x); h0.y = __float2half_rn(v.y);
    h1.x = __float2half_rn(v.z); h1.y = __float2half_rn(v.w);
    ((__half2*)g_xh)[2 * i]     = h0;
    ((__half2*)g_xh)[2 * i + 1] = h1;
}

// transpose: W [E][K][N] fp32 -> [E][N][K] fp16 (residual dropped)
template <int K, int N, bool W1SEL>
__global__ void convert_w_kernel(const float* __restrict__ W) {
    __shared__ float t[32][33];
    int e = blockIdx.z;
    int n0 = blockIdx.x * 32, k0 = blockIdx.y * 32;
    int tx = threadIdx.x, ty = threadIdx.y;  // 32 x 8
    const float* Wp = W + (size_t)e * K * N;
#pragma unroll
    for (int i = 0; i < 4; i++)
        t[ty + 8 * i][tx] = Wp[(size_t)(k0 + ty + 8 * i) * N + n0 + tx];
    __syncthreads();
    __half* oh = (W1SEL ? g_w1h : g_w2h) + (size_t)e * N * K;
    int n_l = (threadIdx.y * 4) + (tx >> 3);        // 0..31
    int k_l = (tx & 7) * 2;                          // even k, pairs
#pragma unroll
    for (int rep = 0; rep < 2; rep++) {
        int kk = k_l + rep * 16;
        __half2 h;
        h.x = __float2half_rn(t[kk][n_l]);
        h.y = __float2half_rn(t[kk + 1][n_l]);
        size_t o = (size_t)(n0 + n_l) * K + k0 + kk;
        *(__half2*)(oh + o) = h;
    }
}

// ---------------- 3) fp16 single-MMA grouped GEMM (R6-proven mainloop shape) -
// BM=128, BN=128, BK=32. 256 threads = 8 warps (2 M x 4 N), warp tile 64x32.
// SMEM stage: A | B, each 128 rows x 40 fp16 (80B padded rows).
// 2-stage cp.async, occupancy 2, low-liveness fragment loop.
#define ROWB   80
#define TILEB  (128 * ROWB)          // 10240 B
#define STAGEB (2 * TILEB)           // 20480 B
#define SMEMB  (2 * STAGEB + 512)    // 41472 B; 2 CTAs = 83KB < 228KB

template <int KDIM>
__device__ __forceinline__ void stage_load(uint32_t sb, int k0,
                                           const __half* __restrict__ A,
                                           const __half* __restrict__ B,
                                           const int* __restrict__ srow, int n0, int tid) {
#pragma unroll
    for (int half_ = 0; half_ < 2; half_++) {
        int c = tid + half_ * 256;       // 0..511
        int r = c >> 2, j = c & 3;
        uint32_t so = (uint32_t)(r * ROWB + j * 16);
        size_t ga = (size_t)srow[r] * KDIM + k0 + j * 8;
        size_t gb = (size_t)(n0 + r) * KDIM + k0 + j * 8;
        cp16(sb + so,         A + ga);
        cp16(sb + TILEB + so, B + gb);
    }
}

template <int KDIM, int NDIM, bool G1>
__global__ void __launch_bounds__(256, 2)
moe_gemm(const float* __restrict__ bias) {
    const int e = blockIdx.z;
    const int cnt = g_cnt[e];
    const int m0 = blockIdx.y * 128;
    if (m0 >= cnt) return;
    const int n0 = blockIdx.x * 128;
    constexpr int NT = KDIM / 32;

    extern __shared__ char smem[];
    const uint32_t sb = smem_u32(smem);
    const int tid = threadIdx.x, wid = tid >> 5, lane = tid & 31;
    const int warp_m = wid >> 2, warp_n = wid & 3;
    const int g = lane >> 2, tg = lane & 3;
    int* srow = (int*)(smem + 2 * STAGEB);

    if (tid < 128) {
        int rr = min(m0 + tid, cnt - 1);
        srow[tid] = G1 ? g_tok[e][rr] : (e * TOKENS + rr);
    }
    __syncthreads();

    const __half* A = G1 ? g_xh : g_hh;
    const __half* B = (G1 ? g_w1h : g_w2h) + (size_t)e * NDIM * KDIM;

    float acc[4][4][4];
#pragma unroll
    for (int i = 0; i < 4; i++)
#pragma unroll
        for (int j = 0; j < 4; j++)
#pragma unroll
            for (int k = 0; k < 4; k++) acc[i][j][k] = 0.f;

    stage_load<KDIM>(sb, 0, A, B, srow, n0, tid);
    cp_commit();

    const int aRowBase = warp_m * 64 + g;
    const int bRowBase = warp_n * 32 + g;

    for (int it = 0; it < NT; it++) {
        cp_wait0();
        __syncthreads();
        if (it + 1 < NT) {
            stage_load<KDIM>(sb + ((it + 1) & 1) * STAGEB, (it + 1) * 32,
                             A, B, srow, n0, tid);
            cp_commit();
        }
        const char* st = smem + (it & 1) * STAGEB;
#pragma unroll
        for (int ks = 0; ks < 2; ks++) {
            const int colb = (ks * 16 + tg * 2) * 2;   // byte offset within row
            uint32_t bh[4][2];
#pragma unroll
            for (int nf = 0; nf < 4; nf++) {
                int ro = (bRowBase + nf * 8) * ROWB + colb;
                bh[nf][0] = *(const uint32_t*)(st + TILEB + ro);
                bh[nf][1] = *(const uint32_t*)(st + TILEB + ro + 16);
            }
#pragma unroll
            for (int mf = 0; mf < 4; mf++) {
                int ro = (aRowBase + mf * 16) * ROWB + colb;
                uint32_t a[4];
                a[0] = *(const uint32_t*)(st + ro);
                a[1] = *(const uint32_t*)(st + ro + 8 * ROWB);
                a[2] = *(const uint32_t*)(st + ro + 16);
                a[3] = *(const uint32_t*)(st + ro + 8 * ROWB + 16);
#pragma unroll
                for (int nf = 0; nf < 4; nf++)
                    MMA_F16(acc[mf][nf], a, bh[nf]);
            }
        }
        __syncthreads();
    }

    // ---------------- epilogue ----------------
#pragma unroll
    for (int mf = 0; mf < 4; mf++) {
        int r0 = m0 + warp_m * 64 + mf * 16 + g;
        int r1 = r0 + 8;
#pragma unroll
        for (int nf = 0; nf < 4; nf++) {
            int col = n0 + warp_n * 32 + nf * 8 + tg * 2;
            float bv0 = bias[e * NDIM + col];
            float bv1 = bias[e * NDIM + col + 1];
#pragma unroll
            for (int h = 0; h < 2; h++) {
                int r = h ? r1 : r0;
                if (r >= cnt) continue;
                float v0 = acc[mf][nf][2 * h]     + bv0;
                float v1 = acc[mf][nf][2 * h + 1] + bv1;
                if (G1) {
                    v0 = fmaxf(v0, 0.f);
                    v1 = fmaxf(v1, 0.f);
                    __half2 hh;
                    hh.x = __float2half_rn(v0);
                    hh.y = __float2half_rn(v1);
                    size_t o = ((size_t)(e * TOKENS + r)) * DF + col;
                    *(__half2*)(g_hh + o) = hh;
                } else {
                    int token = g_tok[e][r];
                    int slot  = g_slot[e][r];
                    float* dst = g_buf + ((size_t)slot * TOKENS + token) * DM + col;
                    *(float2*)dst = make_float2(v0, v1);
                }
            }
        }
    }
}

// ---------------- 4) combine ----------------
__global__ void combine_kernel(float* __restrict__ out) {
    int i = blockIdx.x * blockDim.x + threadIdx.x;
    const float4* b0 = (const float4*)g_buf;
    const float4* b1 = (const float4*)(g_buf + (size_t)TOKENS * DM);
    float4 u = b0[i], v = b1[i];
    ((float4*)out)[i] = make_float4(u.x + v.x, u.y + v.y, u.z + v.z, u.w + v.w);
}

// ---------------- host ----------------
extern "C" void kernel_launch(void* const* d_in, const int* in_sizes, int n_in,
                              void* d_out, int out_size) {
    const float* x  = (const float*)d_in[0];
    const float* Wg = (const float*)d_in[1];
    const float* bg = (const float*)d_in[2];
    const float* W1 = (const float*)d_in[3];
    const float* b1 = (const float*)d_in[4];
    const float* W2 = (const float*)d_in[5];
    const float* b2 = (const float*)d_in[6];
    float* out = (float*)d_out;

    cudaFuncSetAttribute(moe_gemm<DM, DF, true>,
                         cudaFuncAttributeMaxDynamicSharedMemorySize, SMEMB);
    cudaFuncSetAttribute(moe_gemm<DF, DM, false>,
                         cudaFuncAttributeMaxDynamicSharedMemorySize, SMEMB);

    zero_cnt_kernel<<<1, 32>>>();
    route_kernel<<<TOKENS / 8, 256>>>(x, Wg, bg);

    convert_x_kernel<<<TOKENS * DM / 4 / 256, 256>>>(x);
    convert_w_kernel<DM, DF, true><<<dim3(DF / 32, DM / 32, NE), dim3(32, 8)>>>(W1);
    convert_w_kernel<DF, DM, false><<<dim3(DM / 32, DF / 32, NE), dim3(32, 8)>>>(W2);

    // GEMM1: h = relu(gather(x) @ W1h + b1) -> g_hh (fp16)
    moe_gemm<DM, DF, true><<<dim3(DF / 128, TOKENS / 128, NE), 256, SMEMB>>>(b1);
    // GEMM2: y = h @ W2h + b2 -> scatter into g_buf
    moe_gemm<DF, DM, false><<<dim3(DM / 128, TOKENS / 128, NE), 256, SMEMB>>>(b2);

    combine_kernel<<<(TOKENS * DM / 4) / 256, 256>>>(out);
}

// round 10
// speedup vs baseline: 1.5371x; 1.0555x over previous
#include <cuda_runtime.h>
#include <cuda_fp16.h>
#include <cstdint>

#define TOKENS 4096
#define DM 1024
#define DF 4096
#define NE 8

// ---------------- device scratch (static, no runtime alloc) ----------------
__device__ int g_cnt[NE];
__device__ int g_tok[NE][TOKENS];
__device__ int g_slot[NE][TOKENS];
__device__ __align__(16) __half g_xh[(size_t)TOKENS * DM];
__device__ __align__(16) __half g_w1h[(size_t)NE * DF * DM];   // [E][N=DF][K=DM]
__device__ __align__(16) __half g_w2h[(size_t)NE * DM * DF];   // [E][N=DM][K=DF]
__device__ __align__(16) __half g_hh[(size_t)NE * TOKENS * DF];
__device__ __align__(16) float  g_buf[(size_t)2 * TOKENS * DM];

// ---------------- helpers ----------------
__device__ __forceinline__ uint32_t smem_u32(const void* p) {
    uint32_t a;
    asm("{ .reg .u64 t; cvta.to.shared.u64 t, %1; cvt.u32.u64 %0, t; }" : "=r"(a) : "l"(p));
    return a;
}
__device__ __forceinline__ void cp16(uint32_t s, const void* g) {
    asm volatile("cp.async.cg.shared.global [%0], [%1], 16;" :: "r"(s), "l"(g) : "memory");
}
__device__ __forceinline__ void cp_commit() {
    asm volatile("cp.async.commit_group;" ::: "memory");
}
__device__ __forceinline__ void cp_wait0() {
    asm volatile("cp.async.wait_group 0;" ::: "memory");
}
#define MMA_F16(acc, a, b)                                                       \
    asm volatile(                                                                \
        "mma.sync.aligned.m16n8k16.row.col.f32.f16.f16.f32 "                     \
        "{%0,%1,%2,%3},{%4,%5,%6,%7},{%8,%9},{%0,%1,%2,%3};"                     \
        : "+f"((acc)[0]), "+f"((acc)[1]), "+f"((acc)[2]), "+f"((acc)[3])         \
        : "r"((a)[0]), "r"((a)[1]), "r"((a)[2]), "r"((a)[3]),                    \
          "r"((b)[0]), "r"((b)[1]))

// ---------------- shared GEMM config ----------------
#define ROWB   80
#define TILEB  (128 * ROWB)          // 10240 B
#define STAGEB (2 * TILEB)           // 20480 B
#define SMEMB  (2 * STAGEB + 512)    // 41472 B; 2 CTAs/SM

// ---------------- transpose+convert tile body (R9-proven pattern) ----------
__device__ __forceinline__ void conv_tile(const float* __restrict__ Wp,
                                          __half* __restrict__ oh,
                                          int K, int N, int n0, int k0,
                                          int tid, float (*t)[33]) {
    int tx = tid & 31, ty = tid >> 5;   // 32 x 8
#pragma unroll
    for (int i = 0; i < 4; i++)
        t[ty + 8 * i][tx] = Wp[(size_t)(k0 + ty + 8 * i) * N + n0 + tx];
    __syncthreads();
    int n_l = ty * 4 + (tx >> 3);
    int k_l = (tx & 7) * 2;
#pragma unroll
    for (int rep = 0; rep < 2; rep++) {
        int kk = k_l + rep * 16;
        __half2 h;
        h.x = __float2half_rn(t[kk][n_l]);
        h.y = __float2half_rn(t[kk + 1][n_l]);
        *(__half2*)(oh + (size_t)(n0 + n_l) * K + k0 + kk) = h;
    }
}

// ---------------- 0) zero counters ----------------
__global__ void zero_cnt_kernel() {
    if (threadIdx.x < NE) g_cnt[threadIdx.x] = 0;
}

// ---------------- 1) fused prep: route | convert_x | convert_w1 ------------
// blocks [0,512)           : routing (8 tokens per block, 1 warp/token)
// blocks [512, 4608)       : x fp32 -> fp16
// blocks [4608, 12800)     : W1 transpose+convert, 4 k-tiles per block
__global__ void prep_kernel(const float* __restrict__ x,
                            const float* __restrict__ Wg,
                            const float* __restrict__ bg,
                            const float* __restrict__ W1) {
    __shared__ float t[32][33];
    const int bx = blockIdx.x;
    const int tid = threadIdx.x;

    if (bx < 512) {
        // ---- routing ----
        int warp = tid >> 5, lane = tid & 31;
        int token = bx * 8 + warp;
        float acc[NE];
#pragma unroll
        for (int e = 0; e < NE; e++) acc[e] = 0.f;
        const float* xrow = x + (size_t)token * DM;
        for (int k = lane; k < DM; k += 32) {
            float xv = xrow[k];
            const float* wr = Wg + (size_t)k * NE;
#pragma unroll
            for (int e = 0; e < NE; e++) acc[e] += xv * wr[e];
        }
#pragma unroll
        for (int e = 0; e < NE; e++)
#pragma unroll
            for (int o = 16; o > 0; o >>= 1)
                acc[e] += __shfl_xor_sync(0xffffffffu, acc[e], o);
        if (lane == 0) {
            float lg[NE];
#pragma unroll
            for (int e = 0; e < NE; e++) lg[e] = acc[e] + bg[e];
            int e0 = 0;
#pragma unroll
            for (int e = 1; e < NE; e++) if (lg[e] > lg[e0]) e0 = e;
            int e1 = (e0 == 0) ? 1 : 0;
#pragma unroll
            for (int e = 0; e < NE; e++) if (e != e0 && lg[e] > lg[e1]) e1 = e;
            int p0 = atomicAdd(&g_cnt[e0], 1);
            g_tok[e0][p0] = token; g_slot[e0][p0] = 0;
            int p1 = atomicAdd(&g_cnt[e1], 1);
            g_tok[e1][p1] = token; g_slot[e1][p1] = 1;
        }
    } else if (bx < 4608) {
        // ---- convert x ----
        int i = (bx - 512) * 256 + tid;          // float4 index
        float4 v = ((const float4*)x)[i];
        __half2 h0, h1;
        h0.x = __float2half_rn(v.x); h0.y = __float2half_rn(v.y);
        h1.x = __float2half_rn(v.z); h1.y = __float2half_rn(v.w);
        ((__half2*)g_xh)[2 * i]     = h0;
        ((__half2*)g_xh)[2 * i + 1] = h1;
    } else {
        // ---- convert W1: [E][K=DM][N=DF] -> [E][N][K] fp16 ----
        int j = bx - 4608;                       // [0, 8192)
        int e = j >> 10;
        int rem = j & 1023;
        int n_t = rem & 127;                     // 128 n-tiles
        int k_t4 = rem >> 7;                     // 8 groups of 4 k-tiles
        const float* Wp = W1 + (size_t)e * DM * DF;
        __half* oh = g_w1h + (size_t)e * DF * DM;
#pragma unroll
        for (int i = 0; i < 4; i++) {
            __syncthreads();
            conv_tile(Wp, oh, DM, DF, n_t * 32, (k_t4 * 4 + i) * 32, tid, t);
        }
    }
}

// ---------------- GEMM core (R9 mainloop, byte-identical math) --------------
template <int KDIM, bool G1>
__device__ __forceinline__ void stage_load(uint32_t sb, int k0,
                                           const __half* __restrict__ A,
                                           const __half* __restrict__ B,
                                           const int* __restrict__ srow, int aBase,
                                           int n0, int tid) {
#pragma unroll
    for (int half_ = 0; half_ < 2; half_++) {
        int c = tid + half_ * 256;       // 0..511
        int r = c >> 2, j = c & 3;
        uint32_t so = (uint32_t)(r * ROWB + j * 16);
        int arow = G1 ? srow[r] : (aBase + r);
        size_t ga = (size_t)arow * KDIM + k0 + j * 8;
        size_t gb = (size_t)(n0 + r) * KDIM + k0 + j * 8;
        cp16(sb + so,         A + ga);
        cp16(sb + TILEB + so, B + gb);
    }
}

template <int KDIM, int NDIM, bool G1>
__device__ __forceinline__ void gemm_body(const float* __restrict__ bias,
                                          char* smem, int e, int m0, int n0) {
    const int cnt = g_cnt[e];
    if (m0 >= cnt) return;
    constexpr int NT = KDIM / 32;

    const uint32_t sb = smem_u32(smem);
    const int tid = threadIdx.x, wid = tid >> 5, lane = tid & 31;
    const int warp_m = wid >> 2, warp_n = wid & 3;
    const int g = lane >> 2, tg = lane & 3;
    int* srow = (int*)(smem + 2 * STAGEB);
    const int aBase = e * TOKENS + m0;

    if (G1) {
        if (tid < 128) {
            int rr = min(m0 + tid, cnt - 1);
            srow[tid] = g_tok[e][rr];
        }
        __syncthreads();
    }

    const __half* A = G1 ? g_xh : g_hh;
    const __half* B = (G1 ? g_w1h : g_w2h) + (size_t)e * NDIM * KDIM;

    float acc[4][4][4];
#pragma unroll
    for (int i = 0; i < 4; i++)
#pragma unroll
        for (int j = 0; j < 4; j++)
#pragma unroll
            for (int k = 0; k < 4; k++) acc[i][j][k] = 0.f;

    stage_load<KDIM, G1>(sb, 0, A, B, srow, aBase, n0, tid);
    cp_commit();

    const int aRowBase = warp_m * 64 + g;
    const int bRowBase = warp_n * 32 + g;

    for (int it = 0; it < NT; it++) {
        cp_wait0();
        __syncthreads();
        if (it + 1 < NT) {
            stage_load<KDIM, G1>(sb + ((it + 1) & 1) * STAGEB, (it + 1) * 32,
                                 A, B, srow, aBase, n0, tid);
            cp_commit();
        }
        const char* st = smem + (it & 1) * STAGEB;
#pragma unroll
        for (int ks = 0; ks < 2; ks++) {
            const int colb = (ks * 16 + tg * 2) * 2;   // byte offset within row
            uint32_t bh[4][2];
#pragma unroll
            for (int nf = 0; nf < 4; nf++) {
                int ro = (bRowBase + nf * 8) * ROWB + colb;
                bh[nf][0] = *(const uint32_t*)(st + TILEB + ro);
                bh[nf][1] = *(const uint32_t*)(st + TILEB + ro + 16);
            }
#pragma unroll
            for (int mf = 0; mf < 4; mf++) {
                int ro = (aRowBase + mf * 16) * ROWB + colb;
                uint32_t a[4];
                a[0] = *(const uint32_t*)(st + ro);
                a[1] = *(const uint32_t*)(st + ro + 8 * ROWB);
                a[2] = *(const uint32_t*)(st + ro + 16);
                a[3] = *(const uint32_t*)(st + ro + 8 * ROWB + 16);
#pragma unroll
                for (int nf = 0; nf < 4; nf++)
                    MMA_F16(acc[mf][nf], a, bh[nf]);
            }
        }
        __syncthreads();
    }

    // epilogue
#pragma unroll
    for (int mf = 0; mf < 4; mf++) {
        int r0 = m0 + warp_m * 64 + mf * 16 + g;
        int r1 = r0 + 8;
#pragma unroll
        for (int nf = 0; nf < 4; nf++) {
            int col = n0 + warp_n * 32 + nf * 8 + tg * 2;
            float bv0 = bias[e * NDIM + col];
            float bv1 = bias[e * NDIM + col + 1];
#pragma unroll
            for (int h = 0; h < 2; h++) {
                int r = h ? r1 : r0;
                if (r >= cnt) continue;
                float v0 = acc[mf][nf][2 * h]     + bv0;
                float v1 = acc[mf][nf][2 * h + 1] + bv1;
                if (G1) {
                    v0 = fmaxf(v0, 0.f);
                    v1 = fmaxf(v1, 0.f);
                    __half2 hh;
                    hh.x = __float2half_rn(v0);
                    hh.y = __float2half_rn(v1);
                    size_t o = ((size_t)(e * TOKENS + r)) * DF + col;
                    *(__half2*)(g_hh + o) = hh;
                } else {
                    int token = g_tok[e][r];
                    int slot  = g_slot[e][r];
                    float* dst = g_buf + ((size_t)slot * TOKENS + token) * DM + col;
                    *(float2*)dst = make_float2(v0, v1);
                }
            }
        }
    }
}

// ---------------- 2) GEMM1 fused with convert_w2 ---------------------------
// z in [0,8): GEMM1 expert z. z in [8,16): W2 transpose+convert for expert z-8.
__global__ void __launch_bounds__(256, 2)
gemm1_fused(const float* __restrict__ b1, const float* __restrict__ W2) {
    extern __shared__ char smem[];
    if (blockIdx.z >= 8) {
        int e = blockIdx.z - 8;
        int b = blockIdx.y * 32 + blockIdx.x;    // [0, 1024)
        int n_t = b & 31;                        // 32 n-tiles (N=DM)
        int k_t4 = b >> 5;                       // 32 groups of 4 k-tiles (K=DF)
        const float* Wp = W2 + (size_t)e * DF * DM;
        __half* oh = g_w2h + (size_t)e * DM * DF;
        float (*t)[33] = (float(*)[33])smem;
        int tid = threadIdx.x;
#pragma unroll
        for (int i = 0; i < 4; i++) {
            __syncthreads();
            conv_tile(Wp, oh, DF, DM, n_t * 32, (k_t4 * 4 + i) * 32, tid, t);
        }
        return;
    }
    gemm_body<DM, DF, true>(b1, smem, blockIdx.z, blockIdx.y * 128, blockIdx.x * 128);
}

// ---------------- 3) GEMM2 ----------------
__global__ void __launch_bounds__(256, 2)
gemm2_kernel(const float* __restrict__ b2) {
    extern __shared__ char smem[];
    gemm_body<DF, DM, false>(b2, smem, blockIdx.z, blockIdx.y * 128, blockIdx.x * 128);
}

// ---------------- 4) combine ----------------
__global__ void combine_kernel(float* __restrict__ out) {
    int i = blockIdx.x * blockDim.x + threadIdx.x;
    const float4* b0 = (const float4*)g_buf;
    const float4* b1 = (const float4*)(g_buf + (size_t)TOKENS * DM);
    float4 u = b0[i], v = b1[i];
    ((float4*)out)[i] = make_float4(u.x + v.x, u.y + v.y, u.z + v.z, u.w + v.w);
}

// ---------------- host ----------------
extern "C" void kernel_launch(void* const* d_in, const int* in_sizes, int n_in,
                              void* d_out, int out_size) {
    const float* x  = (const float*)d_in[0];
    const float* Wg = (const float*)d_in[1];
    const float* bg = (const float*)d_in[2];
    const float* W1 = (const float*)d_in[3];
    const float* b1 = (const float*)d_in[4];
    const float* W2 = (const float*)d_in[5];
    const float* b2 = (const float*)d_in[6];
    float* out = (float*)d_out;

    cudaFuncSetAttribute(gemm1_fused,
                         cudaFuncAttributeMaxDynamicSharedMemorySize, SMEMB);
    cudaFuncSetAttribute(gemm2_kernel,
                         cudaFuncAttributeMaxDynamicSharedMemorySize, SMEMB);

    zero_cnt_kernel<<<1, 32>>>();
    // route | convert_x | convert_w1 (all independent, one launch)
    prep_kernel<<<12800, 256>>>(x, Wg, bg, W1);
    // GEMM1 (z 0..7) fused with convert_w2 (z 8..15)
    gemm1_fused<<<dim3(DF / 128, TOKENS / 128, 16), 256, SMEMB>>>(b1, W2);
    // GEMM2: y = h @ W2h + b2 -> scatter into g_buf
    gemm2_kernel<<<dim3(DM / 128, TOKENS / 128, NE), 256, SMEMB>>>(b2);
    combine_kernel<<<(TOKENS * DM / 4) / 256, 256>>>(out);
}

// round 11
// speedup vs baseline: 1.6267x; 1.0583x over previous
#include <cuda_runtime.h>
#include <cuda_fp16.h>
#include <cstdint>

#define TOKENS 4096
#define DM 1024
#define DF 4096
#define NE 8

// ---------------- device scratch (static, no runtime alloc) ----------------
__device__ int g_cnt[NE];
__device__ int g_tok[NE][TOKENS];
__device__ int g_slot[NE][TOKENS];
__device__ __align__(16) __half g_xh[(size_t)TOKENS * DM];
__device__ __align__(16) __half g_w1h[(size_t)NE * DF * DM];   // [E][N=DF][K=DM]
__device__ __align__(16) __half g_w2h[(size_t)NE * DM * DF];   // [E][N=DM][K=DF]
__device__ __align__(16) __half g_hh[(size_t)NE * TOKENS * DF];
__device__ __align__(16) float  g_buf[(size_t)2 * TOKENS * DM];

// ---------------- helpers ----------------
__device__ __forceinline__ uint32_t smem_u32(const void* p) {
    uint32_t a;
    asm("{ .reg .u64 t; cvta.to.shared.u64 t, %1; cvt.u32.u64 %0, t; }" : "=r"(a) : "l"(p));
    return a;
}
__device__ __forceinline__ void cp16(uint32_t s, const void* g) {
    asm volatile("cp.async.cg.shared.global [%0], [%1], 16;" :: "r"(s), "l"(g) : "memory");
}
__device__ __forceinline__ void cp_commit() {
    asm volatile("cp.async.commit_group;" ::: "memory");
}
__device__ __forceinline__ void cp_wait1() {
    asm volatile("cp.async.wait_group 1;" ::: "memory");
}
#define MMA_F16(acc, a, b)                                                       \
    asm volatile(                                                                \
        "mma.sync.aligned.m16n8k16.row.col.f32.f16.f16.f32 "                     \
        "{%0,%1,%2,%3},{%4,%5,%6,%7},{%8,%9},{%0,%1,%2,%3};"                     \
        : "+f"((acc)[0]), "+f"((acc)[1]), "+f"((acc)[2]), "+f"((acc)[3])         \
        : "r"((a)[0]), "r"((a)[1]), "r"((a)[2]), "r"((a)[3]),                    \
          "r"((b)[0]), "r"((b)[1]))

// ---------------- shared GEMM config ----------------
#define ROWB   80
#define TILEB  (128 * ROWB)          // 10240 B
#define STAGEB (2 * TILEB)           // 20480 B (A tile + B tile)
#define NSTAGE 3
#define SMEMB  (NSTAGE * STAGEB + 512)   // 61952 B; 2 CTAs = 124KB < 228KB

// ---------------- transpose+convert tile body ----------
__device__ __forceinline__ void conv_tile(const float* __restrict__ Wp,
                                          __half* __restrict__ oh,
                                          int K, int N, int n0, int k0,
                                          int tid, float (*t)[33]) {
    int tx = tid & 31, ty = tid >> 5;   // 32 x 8
#pragma unroll
    for (int i = 0; i < 4; i++)
        t[ty + 8 * i][tx] = Wp[(size_t)(k0 + ty + 8 * i) * N + n0 + tx];
    __syncthreads();
    int n_l = ty * 4 + (tx >> 3);
    int k_l = (tx & 7) * 2;
#pragma unroll
    for (int rep = 0; rep < 2; rep++) {
        int kk = k_l + rep * 16;
        __half2 h;
        h.x = __float2half_rn(t[kk][n_l]);
        h.y = __float2half_rn(t[kk + 1][n_l]);
        *(__half2*)(oh + (size_t)(n0 + n_l) * K + k0 + kk) = h;
    }
}

// ---------------- 0) zero counters ----------------
__global__ void zero_cnt_kernel() {
    if (threadIdx.x < NE) g_cnt[threadIdx.x] = 0;
}

// ---------------- 1) fused prep: route | convert_x | convert_w1 ------------
__global__ void prep_kernel(const float* __restrict__ x,
                            const float* __restrict__ Wg,
                            const float* __restrict__ bg,
                            const float* __restrict__ W1) {
    __shared__ float t[32][33];
    const int bx = blockIdx.x;
    const int tid = threadIdx.x;

    if (bx < 512) {
        // ---- routing ----
        int warp = tid >> 5, lane = tid & 31;
        int token = bx * 8 + warp;
        float acc[NE];
#pragma unroll
        for (int e = 0; e < NE; e++) acc[e] = 0.f;
        const float* xrow = x + (size_t)token * DM;
        for (int k = lane; k < DM; k += 32) {
            float xv = xrow[k];
            const float* wr = Wg + (size_t)k * NE;
#pragma unroll
            for (int e = 0; e < NE; e++) acc[e] += xv * wr[e];
        }
#pragma unroll
        for (int e = 0; e < NE; e++)
#pragma unroll
            for (int o = 16; o > 0; o >>= 1)
                acc[e] += __shfl_xor_sync(0xffffffffu, acc[e], o);
        if (lane == 0) {
            float lg[NE];
#pragma unroll
            for (int e = 0; e < NE; e++) lg[e] = acc[e] + bg[e];
            int e0 = 0;
#pragma unroll
            for (int e = 1; e < NE; e++) if (lg[e] > lg[e0]) e0 = e;
            int e1 = (e0 == 0) ? 1 : 0;
#pragma unroll
            for (int e = 0; e < NE; e++) if (e != e0 && lg[e] > lg[e1]) e1 = e;
            int p0 = atomicAdd(&g_cnt[e0], 1);
            g_tok[e0][p0] = token; g_slot[e0][p0] = 0;
            int p1 = atomicAdd(&g_cnt[e1], 1);
            g_tok[e1][p1] = token; g_slot[e1][p1] = 1;
        }
    } else if (bx < 4608) {
        // ---- convert x ----
        int i = (bx - 512) * 256 + tid;          // float4 index
        float4 v = ((const float4*)x)[i];
        __half2 h0, h1;
        h0.x = __float2half_rn(v.x); h0.y = __float2half_rn(v.y);
        h1.x = __float2half_rn(v.z); h1.y = __float2half_rn(v.w);
        ((__half2*)g_xh)[2 * i]     = h0;
        ((__half2*)g_xh)[2 * i + 1] = h1;
    } else {
        // ---- convert W1 ----
        int j = bx - 4608;                       // [0, 8192)
        int e = j >> 10;
        int rem = j & 1023;
        int n_t = rem & 127;
        int k_t4 = rem >> 7;
        const float* Wp = W1 + (size_t)e * DM * DF;
        __half* oh = g_w1h + (size_t)e * DF * DM;
#pragma unroll
        for (int i = 0; i < 4; i++) {
            __syncthreads();
            conv_tile(Wp, oh, DM, DF, n_t * 32, (k_t4 * 4 + i) * 32, tid, t);
        }
    }
}

// ---------------- GEMM core: 3-stage cp.async, wait_group 1, 1 sync/iter ----
template <int KDIM, bool G1>
__device__ __forceinline__ void stage_load(uint32_t sb, int k0,
                                           const __half* __restrict__ A,
                                           const __half* __restrict__ B,
                                           const int* __restrict__ srow, int aBase,
                                           int n0, int tid) {
#pragma unroll
    for (int half_ = 0; half_ < 2; half_++) {
        int c = tid + half_ * 256;       // 0..511
        int r = c >> 2, j = c & 3;
        uint32_t so = (uint32_t)(r * ROWB + j * 16);
        int arow = G1 ? srow[r] : (aBase + r);
        size_t ga = (size_t)arow * KDIM + k0 + j * 8;
        size_t gb = (size_t)(n0 + r) * KDIM + k0 + j * 8;
        cp16(sb + so,         A + ga);
        cp16(sb + TILEB + so, B + gb);
    }
}

template <int KDIM, int NDIM, bool G1>
__device__ __forceinline__ void gemm_body(const float* __restrict__ bias,
                                          char* smem, int e, int m0, int n0) {
    const int cnt = g_cnt[e];
    if (m0 >= cnt) return;
    constexpr int NT = KDIM / 32;

    const uint32_t sb = smem_u32(smem);
    const int tid = threadIdx.x, wid = tid >> 5, lane = tid & 31;
    const int warp_m = wid >> 2, warp_n = wid & 3;
    const int g = lane >> 2, tg = lane & 3;
    int* srow = (int*)(smem + NSTAGE * STAGEB);
    const int aBase = e * TOKENS + m0;

    if (G1) {
        if (tid < 128) {
            int rr = min(m0 + tid, cnt - 1);
            srow[tid] = g_tok[e][rr];
        }
        __syncthreads();
    }

    const __half* A = G1 ? g_xh : g_hh;
    const __half* B = (G1 ? g_w1h : g_w2h) + (size_t)e * NDIM * KDIM;

    float acc[4][4][4];
#pragma unroll
    for (int i = 0; i < 4; i++)
#pragma unroll
        for (int j = 0; j < 4; j++)
#pragma unroll
            for (int k = 0; k < 4; k++) acc[i][j][k] = 0.f;

    // prologue: stages 0, 1 in flight
    stage_load<KDIM, G1>(sb, 0, A, B, srow, aBase, n0, tid);
    cp_commit();
    stage_load<KDIM, G1>(sb + STAGEB, 32, A, B, srow, aBase, n0, tid);
    cp_commit();

    const int aRowBase = warp_m * 64 + g;
    const int bRowBase = warp_n * 32 + g;

    int slot = 0;
    for (int it = 0; it < NT; it++) {
        cp_wait1();                  // stage `it` resident (committed 2 groups ago)
        __syncthreads();             // also fences compute of stage it-1 (slot reused below)
        if (it + 2 < NT) {
            int ns = slot + 2; if (ns >= NSTAGE) ns -= NSTAGE;
            stage_load<KDIM, G1>(sb + ns * STAGEB, (it + 2) * 32,
                                 A, B, srow, aBase, n0, tid);
        }
        cp_commit();                 // unconditional: pending count stays exact

        const char* st = smem + slot * STAGEB;
#pragma unroll
        for (int ks = 0; ks < 2; ks++) {
            const int colb = (ks * 16 + tg * 2) * 2;
            uint32_t bh[4][2];
#pragma unroll
            for (int nf = 0; nf < 4; nf++) {
                int ro = (bRowBase + nf * 8) * ROWB + colb;
                bh[nf][0] = *(const uint32_t*)(st + TILEB + ro);
                bh[nf][1] = *(const uint32_t*)(st + TILEB + ro + 16);
            }
#pragma unroll
            for (int mf = 0; mf < 4; mf++) {
                int ro = (aRowBase + mf * 16) * ROWB + colb;
                uint32_t a[4];
                a[0] = *(const uint32_t*)(st + ro);
                a[1] = *(const uint32_t*)(st + ro + 8 * ROWB);
                a[2] = *(const uint32_t*)(st + ro + 16);
                a[3] = *(const uint32_t*)(st + ro + 8 * ROWB + 16);
#pragma unroll
                for (int nf = 0; nf < 4; nf++)
                    MMA_F16(acc[mf][nf], a, bh[nf]);
            }
        }
        slot++; if (slot >= NSTAGE) slot = 0;
    }

    // epilogue
#pragma unroll
    for (int mf = 0; mf < 4; mf++) {
        int r0 = m0 + warp_m * 64 + mf * 16 + g;
        int r1 = r0 + 8;
#pragma unroll
        for (int nf = 0; nf < 4; nf++) {
            int col = n0 + warp_n * 32 + nf * 8 + tg * 2;
            float bv0 = bias[e * NDIM + col];
            float bv1 = bias[e * NDIM + col + 1];
#pragma unroll
            for (int h = 0; h < 2; h++) {
                int r = h ? r1 : r0;
                if (r >= cnt) continue;
                float v0 = acc[mf][nf][2 * h]     + bv0;
                float v1 = acc[mf][nf][2 * h + 1] + bv1;
                if (G1) {
                    v0 = fmaxf(v0, 0.f);
                    v1 = fmaxf(v1, 0.f);
                    __half2 hh;
                    hh.x = __float2half_rn(v0);
                    hh.y = __float2half_rn(v1);
                    size_t o = ((size_t)(e * TOKENS + r)) * DF + col;
                    *(__half2*)(g_hh + o) = hh;
                } else {
                    int token = g_tok[e][r];
                    int slot2 = g_slot[e][r];
                    float* dst = g_buf + ((size_t)slot2 * TOKENS + token) * DM + col;
                    *(float2*)dst = make_float2(v0, v1);
                }
            }
        }
    }
}

// ---------------- 2) GEMM1 fused with convert_w2 ---------------------------
__global__ void __launch_bounds__(256, 2)
gemm1_fused(const float* __restrict__ b1, const float* __restrict__ W2) {
    extern __shared__ char smem[];
    if (blockIdx.z >= 8) {
        int e = blockIdx.z - 8;
        int b = blockIdx.y * 32 + blockIdx.x;    // [0, 1024)
        int n_t = b & 31;
        int k_t4 = b >> 5;
        const float* Wp = W2 + (size_t)e * DF * DM;
        __half* oh = g_w2h + (size_t)e * DM * DF;
        float (*t)[33] = (float(*)[33])smem;
        int tid = threadIdx.x;
#pragma unroll
        for (int i = 0; i < 4; i++) {
            __syncthreads();
            conv_tile(Wp, oh, DF, DM, n_t * 32, (k_t4 * 4 + i) * 32, tid, t);
        }
        return;
    }
    gemm_body<DM, DF, true>(b1, smem, blockIdx.z, blockIdx.y * 128, blockIdx.x * 128);
}

// ---------------- 3) GEMM2 ----------------
__global__ void __launch_bounds__(256, 2)
gemm2_kernel(const float* __restrict__ b2) {
    extern __shared__ char smem[];
    gemm_body<DF, DM, false>(b2, smem, blockIdx.z, blockIdx.y * 128, blockIdx.x * 128);
}

// ---------------- 4) combine ----------------
__global__ void combine_kernel(float* __restrict__ out) {
    int i = blockIdx.x * blockDim.x + threadIdx.x;
    const float4* b0 = (const float4*)g_buf;
    const float4* b1 = (const float4*)(g_buf + (size_t)TOKENS * DM);
    float4 u = b0[i], v = b1[i];
    ((float4*)out)[i] = make_float4(u.x + v.x, u.y + v.y, u.z + v.z, u.w + v.w);
}

// ---------------- host ----------------
extern "C" void kernel_launch(void* const* d_in, const int* in_sizes, int n_in,
                              void* d_out, int out_size) {
    const float* x  = (const float*)d_in[0];
    const float* Wg = (const float*)d_in[1];
    const float* bg = (const float*)d_in[2];
    const float* W1 = (const float*)d_in[3];
    const float* b1 = (const float*)d_in[4];
    const float* W2 = (const float*)d_in[5];
    const float* b2 = (const float*)d_in[6];
    float* out = (float*)d_out;

    cudaFuncSetAttribute(gemm1_fused,
                         cudaFuncAttributeMaxDynamicSharedMemorySize, SMEMB);
    cudaFuncSetAttribute(gemm2_kernel,
                         cudaFuncAttributeMaxDynamicSharedMemorySize, SMEMB);

    zero_cnt_kernel<<<1, 32>>>();
    prep_kernel<<<12800, 256>>>(x, Wg, bg, W1);
    gemm1_fused<<<dim3(DF / 128, TOKENS / 128, 16), 256, SMEMB>>>(b1, W2);
    gemm2_kernel<<<dim3(DM / 128, TOKENS / 128, NE), 256, SMEMB>>>(b2);
    combine_kernel<<<(TOKENS * DM / 4) / 256, 256>>>(out);
}